// round 2
// baseline (speedup 1.0000x reference)
#include <cuda_runtime.h>
#include <math.h>

#define Bdim 2
#define Tdim 2048
#define Cdim 1024
#define Hdim 16
#define HDdim 64
#define SCALE 0.125f   // (1/ALPHA/sqrt(HD)) * ALPHA  == 1/sqrt(64)

// Scratch (device globals: no allocation allowed in kernel_launch)
__device__ float g_q[Bdim * Tdim * Cdim];
__device__ float g_k[Bdim * Tdim * Cdim];
__device__ float g_v[Bdim * Tdim * Cdim];
__device__ float g_y[Bdim * Tdim * Cdim];

// ---------------------------------------------------------------------------
// GEMM with bias: C[M,N] = A[M,K] @ W[K,N] + b[N]
// 128x128 block tile, BK=8, 256 threads, 8x8 per thread, reg-prefetch pipeline
// ---------------------------------------------------------------------------
#define GM 128
#define GN 128
#define GK 8

__global__ __launch_bounds__(256) void gemm_bias_kernel(
    const float* __restrict__ A, const float* __restrict__ W,
    const float* __restrict__ bias, float* __restrict__ Cout,
    int M, int N, int K)
{
    __shared__ float Ast[GK][GM];   // A tile stored transposed: Ast[k][m]
    __shared__ float Bs[GK][GN];

    const int tid = threadIdx.x;
    const int tx = tid & 15;        // 0..15 -> N direction
    const int ty = tid >> 4;        // 0..15 -> M direction
    const int row0 = blockIdx.y * GM;
    const int col0 = blockIdx.x * GN;

    // gmem staging indices
    const int a_row = tid >> 1;            // 0..127
    const int a_col = (tid & 1) * 4;       // 0 or 4
    const int b_row = tid >> 5;            // 0..7
    const int b_col = (tid & 31) * 4;      // 0..124

    const float* Ap = A + (size_t)(row0 + a_row) * K + a_col;
    const float* Bp = W + (size_t)b_row * N + col0 + b_col;

    float acc[8][8];
#pragma unroll
    for (int i = 0; i < 8; i++)
#pragma unroll
        for (int j = 0; j < 8; j++) acc[i][j] = 0.0f;

    float4 areg = *(const float4*)Ap;
    float4 breg = *(const float4*)Bp;

    const int nk = K / GK;
    for (int kt = 0; kt < nk; ++kt) {
        Ast[a_col + 0][a_row] = areg.x;
        Ast[a_col + 1][a_row] = areg.y;
        Ast[a_col + 2][a_row] = areg.z;
        Ast[a_col + 3][a_row] = areg.w;
        *(float4*)&Bs[b_row][b_col] = breg;
        __syncthreads();

        if (kt + 1 < nk) {
            areg = *(const float4*)(Ap + (kt + 1) * GK);
            breg = *(const float4*)(Bp + (size_t)(kt + 1) * GK * N);
        }

#pragma unroll
        for (int k = 0; k < GK; ++k) {
            float af[8], bf[8];
            *(float4*)&af[0] = *(const float4*)&Ast[k][ty * 8];
            *(float4*)&af[4] = *(const float4*)&Ast[k][ty * 8 + 4];
            *(float4*)&bf[0] = *(const float4*)&Bs[k][tx * 8];
            *(float4*)&bf[4] = *(const float4*)&Bs[k][tx * 8 + 4];
#pragma unroll
            for (int i = 0; i < 8; i++)
#pragma unroll
                for (int j = 0; j < 8; j++)
                    acc[i][j] += af[i] * bf[j];
        }
        __syncthreads();
    }

#pragma unroll
    for (int i = 0; i < 8; i++) {
        size_t r = (size_t)(row0 + ty * 8 + i);
#pragma unroll
        for (int jj = 0; jj < 8; jj += 4) {
            int c = col0 + tx * 8 + jj;
            float4 o;
            o.x = acc[i][jj + 0] + bias[c + 0];
            o.y = acc[i][jj + 1] + bias[c + 1];
            o.z = acc[i][jj + 2] + bias[c + 2];
            o.w = acc[i][jj + 3] + bias[c + 3];
            *(float4*)&Cout[r * N + c] = o;
        }
    }
}

// ---------------------------------------------------------------------------
// Flash attention (causal), fp32. BQ=BK=64, 256 threads (16x16), 4x4 per thread.
// Q/K/V buffers are [B, T, C] where head h occupies columns [h*64, h*64+64).
// S columns (keys) owned strided (tx + 16*j)  -> conflict-free K-row reads.
// O columns (dims) owned contiguous (4*tx+j) -> conflict-free V float4 reads.
// ---------------------------------------------------------------------------
#define BQ 64
#define BK 64
#define KS 68   // smem row stride (floats); 16B-aligned rows, conflict-friendly

extern __shared__ float fsh[];

__global__ __launch_bounds__(256) void flash_kernel(
    const float* __restrict__ Q, const float* __restrict__ Kg,
    const float* __restrict__ V, float* __restrict__ Y)
{
    float* Qs = fsh;                 // [BQ][KS]
    float* Ks = Qs + BQ * KS;        // [BK][KS]
    float* Vs = Ks + BK * KS;        // [BK][KS]
    float* Ps = Vs + BK * KS;        // [BQ][KS]

    const int tid = threadIdx.x;
    const int tx = tid & 15;
    const int ty = tid >> 4;
    const int qt = blockIdx.x;     // q tile (0..31)
    const int h  = blockIdx.y;     // head
    const int b  = blockIdx.z;     // batch
    const int q0 = qt * BQ;

    const float* Qb = Q + ((size_t)b * Tdim) * Cdim + h * HDdim;
    const float* Kb = Kg + ((size_t)b * Tdim) * Cdim + h * HDdim;
    const float* Vb = V + ((size_t)b * Tdim) * Cdim + h * HDdim;

    // Load Q tile (pre-scaled)
    {
        int c = (tid & 15) * 4;
        for (int r = tid >> 4; r < BQ; r += 16) {
            float4 v = *(const float4*)(Qb + (size_t)(q0 + r) * Cdim + c);
            v.x *= SCALE; v.y *= SCALE; v.z *= SCALE; v.w *= SCALE;
            *(float4*)&Qs[r * KS + c] = v;
        }
    }

    float m[4], l[4], O[4][4];
#pragma unroll
    for (int i = 0; i < 4; i++) {
        m[i] = -INFINITY;
        l[i] = 0.0f;
#pragma unroll
        for (int j = 0; j < 4; j++) O[i][j] = 0.0f;
    }

    for (int kt = 0; kt <= qt; ++kt) {
        __syncthreads();   // Q ready (first iter) / previous PV done
        const int k0 = kt * BK;
        {
            int c = (tid & 15) * 4;
            for (int r = tid >> 4; r < BK; r += 16) {
                *(float4*)&Ks[r * KS + c] =
                    *(const float4*)(Kb + (size_t)(k0 + r) * Cdim + c);
                *(float4*)&Vs[r * KS + c] =
                    *(const float4*)(Vb + (size_t)(k0 + r) * Cdim + c);
            }
        }
        __syncthreads();

        // S = Q K^T  (rows: ty*4+i ; cols: tx+16*j)
        float s[4][4];
#pragma unroll
        for (int i = 0; i < 4; i++)
#pragma unroll
            for (int j = 0; j < 4; j++) s[i][j] = 0.0f;

#pragma unroll
        for (int d0 = 0; d0 < HDdim; d0 += 4) {
            float4 qf[4], kf[4];
#pragma unroll
            for (int i = 0; i < 4; i++)
                qf[i] = *(const float4*)&Qs[(ty * 4 + i) * KS + d0];
#pragma unroll
            for (int j = 0; j < 4; j++)
                kf[j] = *(const float4*)&Ks[(tx + 16 * j) * KS + d0];
#pragma unroll
            for (int i = 0; i < 4; i++)
#pragma unroll
                for (int j = 0; j < 4; j++) {
                    s[i][j] += qf[i].x * kf[j].x;
                    s[i][j] += qf[i].y * kf[j].y;
                    s[i][j] += qf[i].z * kf[j].z;
                    s[i][j] += qf[i].w * kf[j].w;
                }
        }

        // Causal mask (only diagonal tile; BQ==BK so q0==k0 there)
        if (kt == qt) {
#pragma unroll
            for (int i = 0; i < 4; i++)
#pragma unroll
                for (int j = 0; j < 4; j++)
                    if (tx + 16 * j > ty * 4 + i) s[i][j] = -INFINITY;
        }

        // Online softmax update + stage P in smem
#pragma unroll
        for (int i = 0; i < 4; i++) {
            float rm = fmaxf(fmaxf(s[i][0], s[i][1]), fmaxf(s[i][2], s[i][3]));
#pragma unroll
            for (int off = 8; off > 0; off >>= 1)
                rm = fmaxf(rm, __shfl_xor_sync(0xffffffffu, rm, off));
            float mn = fmaxf(m[i], rm);
            float corr = __expf(m[i] - mn);
            float p[4];
            float rs = 0.0f;
#pragma unroll
            for (int j = 0; j < 4; j++) {
                p[j] = __expf(s[i][j] - mn);
                rs += p[j];
            }
#pragma unroll
            for (int off = 8; off > 0; off >>= 1)
                rs += __shfl_xor_sync(0xffffffffu, rs, off);
            l[i] = l[i] * corr + rs;
            m[i] = mn;
#pragma unroll
            for (int j = 0; j < 4; j++) O[i][j] *= corr;
            // strided-col stores: conflict-free (consecutive tx -> consecutive addrs)
            Ps[(ty * 4 + i) * KS + tx +  0] = p[0];
            Ps[(ty * 4 + i) * KS + tx + 16] = p[1];
            Ps[(ty * 4 + i) * KS + tx + 32] = p[2];
            Ps[(ty * 4 + i) * KS + tx + 48] = p[3];
        }
        __syncthreads();

        // O += P @ V   (O cols contiguous: 4*tx + j)
#pragma unroll
        for (int k4 = 0; k4 < BK; k4 += 4) {
            float pf[4][4];
#pragma unroll
            for (int i = 0; i < 4; i++)
                *(float4*)&pf[i][0] = *(const float4*)&Ps[(ty * 4 + i) * KS + k4];
#pragma unroll
            for (int kk = 0; kk < 4; kk++) {
                float vf[4];
                *(float4*)&vf[0] = *(const float4*)&Vs[(k4 + kk) * KS + tx * 4];
#pragma unroll
                for (int i = 0; i < 4; i++)
#pragma unroll
                    for (int j = 0; j < 4; j++)
                        O[i][j] += pf[i][kk] * vf[j];
            }
        }
    }

    // Epilogue: O /= l, write to Y [B,T,C]
#pragma unroll
    for (int i = 0; i < 4; i++) {
        float inv = 1.0f / l[i];
        float4 o;
        o.x = O[i][0] * inv;
        o.y = O[i][1] * inv;
        o.z = O[i][2] * inv;
        o.w = O[i][3] * inv;
        *(float4*)&Y[((size_t)b * Tdim + q0 + ty * 4 + i) * Cdim + h * HDdim + tx * 4] = o;
    }
}

// ---------------------------------------------------------------------------
// Launch
// ---------------------------------------------------------------------------
extern "C" void kernel_launch(void* const* d_in, const int* in_sizes, int n_in,
                              void* d_out, int out_size)
{
    const float* query = (const float*)d_in[0];
    const float* key_  = (const float*)d_in[1];
    const float* value = (const float*)d_in[2];
    // d_in[3] = att_mask (causal tril) — causality is applied analytically
    const float* Wq = (const float*)d_in[4];
    const float* bq = (const float*)d_in[5];
    const float* Wk = (const float*)d_in[6];
    const float* bk = (const float*)d_in[7];
    const float* Wv = (const float*)d_in[8];
    const float* bv = (const float*)d_in[9];
    const float* Wp = (const float*)d_in[10];
    const float* bp = (const float*)d_in[11];
    float* out = (float*)d_out;

    float *q, *k, *v, *y;
    cudaGetSymbolAddress((void**)&q, g_q);
    cudaGetSymbolAddress((void**)&k, g_k);
    cudaGetSymbolAddress((void**)&v, g_v);
    cudaGetSymbolAddress((void**)&y, g_y);

    const int M = Bdim * Tdim;   // 4096
    const int N = Cdim;          // 1024
    const int K = Cdim;          // 1024
    dim3 ggrid(N / GN, M / GM);  // (8, 32)

    gemm_bias_kernel<<<ggrid, 256>>>(query, Wq, bq, q, M, N, K);
    gemm_bias_kernel<<<ggrid, 256>>>(key_,  Wk, bk, k, M, N, K);
    gemm_bias_kernel<<<ggrid, 256>>>(value, Wv, bv, v, M, N, K);

    const int fsm = 4 * 64 * KS * (int)sizeof(float);  // 69632 B
    cudaFuncSetAttribute(flash_kernel,
                         cudaFuncAttributeMaxDynamicSharedMemorySize, fsm);
    flash_kernel<<<dim3(Tdim / BQ, Hdim, Bdim), 256, fsm>>>(q, k, v, y);

    gemm_bias_kernel<<<ggrid, 256>>>(y, Wp, bp, out, M, N, K);
}

// round 5
// speedup vs baseline: 1.4913x; 1.4913x over previous
#include <cuda_runtime.h>
#include <cuda_bf16.h>
#include <stdint.h>
#include <math.h>

#define Bdim 2
#define Tdim 2048
#define Cdim 1024
#define Hdim 16
#define HDdim 64
#define SCALE 0.125f   // (1/ALPHA/sqrt(HD)) * ALPHA == 1/sqrt(64)

#define Mrows (Bdim * Tdim)   // 4096

// ---------------- device scratch (no allocation allowed) -------------------
__device__ float g_q[Mrows * Cdim];
__device__ float g_k[Mrows * Cdim];
__device__ float g_v[Mrows * Cdim];
__device__ float g_y[Mrows * Cdim];
__device__ __nv_bfloat16 g_ah[Mrows * Cdim];   // activation hi
__device__ __nv_bfloat16 g_al[Mrows * Cdim];   // activation lo
__device__ __nv_bfloat16 g_wh[Cdim * Cdim];    // W^T hi [N,K]
__device__ __nv_bfloat16 g_wl[Cdim * Cdim];    // W^T lo [N,K]

// ---------------------------------------------------------------------------
// Portable PTX helpers (valid on compute_103 virtual arch)
// ---------------------------------------------------------------------------
__device__ __forceinline__ void cp16(uint32_t dst, const void* src) {
    asm volatile("cp.async.cg.shared.global [%0], [%1], 16;" :: "r"(dst), "l"(src));
}
__device__ __forceinline__ void cp_commit() {
    asm volatile("cp.async.commit_group;" ::: "memory");
}
template <int N>
__device__ __forceinline__ void cp_wait() {
    asm volatile("cp.async.wait_group %0;" :: "n"(N) : "memory");
}
__device__ __forceinline__ void ldm_x4(uint32_t f[4], uint32_t addr) {
    asm volatile("ldmatrix.sync.aligned.m8n8.x4.shared.b16 {%0,%1,%2,%3}, [%4];"
                 : "=r"(f[0]), "=r"(f[1]), "=r"(f[2]), "=r"(f[3]) : "r"(addr));
}
__device__ __forceinline__ void mma_bf16(float c[4], const uint32_t a[4],
                                         const uint32_t b0, const uint32_t b1) {
    asm volatile(
        "mma.sync.aligned.m16n8k16.row.col.f32.bf16.bf16.f32 "
        "{%0,%1,%2,%3}, {%4,%5,%6,%7}, {%8,%9}, {%0,%1,%2,%3};"
        : "+f"(c[0]), "+f"(c[1]), "+f"(c[2]), "+f"(c[3])
        : "r"(a[0]), "r"(a[1]), "r"(a[2]), "r"(a[3]), "r"(b0), "r"(b1));
}

// ---------------------------------------------------------------------------
// Conversion kernels
// ---------------------------------------------------------------------------
__global__ __launch_bounds__(256) void conv_split_kernel(
    const float* __restrict__ x, __nv_bfloat16* __restrict__ h,
    __nv_bfloat16* __restrict__ l, int n4)
{
    int i = blockIdx.x * 256 + threadIdx.x;
    if (i >= n4) return;
    float4 v = ((const float4*)x)[i];
    union { __nv_bfloat16 b[4]; uint2 u; } H, L;
    float vv[4] = {v.x, v.y, v.z, v.w};
#pragma unroll
    for (int j = 0; j < 4; j++) {
        H.b[j] = __float2bfloat16_rn(vv[j]);
        L.b[j] = __float2bfloat16_rn(vv[j] - __bfloat162float(H.b[j]));
    }
    ((uint2*)h)[i] = H.u;
    ((uint2*)l)[i] = L.u;
}

// W [K,N] fp32 -> W^T hi/lo bf16 [N,K]
__global__ __launch_bounds__(256) void conv_wT_kernel(
    const float* __restrict__ W, __nv_bfloat16* __restrict__ ht,
    __nv_bfloat16* __restrict__ lt)
{
    __shared__ float t[32][33];
    int n0 = blockIdx.x * 32, k0 = blockIdx.y * 32;
    int tx = threadIdx.x, ty = threadIdx.y;   // 32 x 8
#pragma unroll
    for (int r = 0; r < 32; r += 8)
        t[ty + r][tx] = W[(size_t)(k0 + ty + r) * Cdim + n0 + tx];
    __syncthreads();
#pragma unroll
    for (int r = 0; r < 32; r += 8) {
        float v = t[tx][ty + r];
        __nv_bfloat16 hb = __float2bfloat16_rn(v);
        size_t o = (size_t)(n0 + ty + r) * Cdim + k0 + tx;
        ht[o] = hb;
        lt[o] = __float2bfloat16_rn(v - __bfloat162float(hb));
    }
}

// ---------------------------------------------------------------------------
// HMMA bf16x3 GEMM: C[M,N] = (Ah+Al)@(Bh+Bl)^T + bias
// CTA 128x128, K-chunk 32, double-buffered cp.async, 8 warps x (64x32) tiles
// Smem tiles row-stride 40 elems (80B) -> conflict-free ldmatrix
// ---------------------------------------------------------------------------
#define BM 128
#define BN 128
#define BKc 32
#define LDT 40
#define TILE_B (128 * LDT * 2)       // 10240 B
#define STG_B (4 * TILE_B)           // 40960 B
#define OFF_AH 0
#define OFF_AL TILE_B
#define OFF_BH (2 * TILE_B)
#define OFF_BL (3 * TILE_B)
#define GEMM_SMEM (2 * STG_B)        // 81920 B
#define NKCH (Cdim / BKc)            // 32

extern __shared__ __align__(128) char gsm[];

__global__ __launch_bounds__(256) void gemm_tc_kernel(
    const __nv_bfloat16* __restrict__ Ah, const __nv_bfloat16* __restrict__ Al,
    const __nv_bfloat16* __restrict__ Bh, const __nv_bfloat16* __restrict__ Bl,
    const float* __restrict__ bias, float* __restrict__ Cout)
{
    const int tid = threadIdx.x;
    const int lane = tid & 31;
    const int wid = tid >> 5;
    const int wm = wid >> 2;          // 0..1  (rows 64 each)
    const int wn = wid & 3;           // 0..3  (cols 32 each)
    const int m0 = blockIdx.y * BM;
    const int n0 = blockIdx.x * BN;
    const uint32_t sb = (uint32_t)__cvta_generic_to_shared(gsm);

    const __nv_bfloat16* srcA[2] = {Ah, Al};
    const __nv_bfloat16* srcB[2] = {Bh, Bl};

    // ---- stage loader: 2048 cp16 per stage, 8 per thread ----
    auto load_stage = [&](int c, int st) {
        const int kc = c * BKc;
        const uint32_t base = sb + st * STG_B;
#pragma unroll
        for (int it = 0; it < 8; it++) {
            int id = tid + it * 256;
            int tile = id >> 9;          // 0..3
            int rem = id & 511;
            int row = rem >> 2;
            int grp = rem & 3;
            uint32_t dst = base + tile * TILE_B + (row * LDT + grp * 8) * 2;
            const __nv_bfloat16* s;
            if (tile < 2) s = srcA[tile] + (size_t)(m0 + row) * Cdim + kc + grp * 8;
            else          s = srcB[tile - 2] + (size_t)(n0 + row) * Cdim + kc + grp * 8;
            cp16(dst, s);
        }
        cp_commit();
    };

    float acc[4][4][4];
#pragma unroll
    for (int i = 0; i < 4; i++)
#pragma unroll
        for (int j = 0; j < 4; j++)
#pragma unroll
            for (int r = 0; r < 4; r++) acc[i][j][r] = 0.0f;

    // ldmatrix lane addressing (element offsets within a tile)
    const int a_r = lane & 15, a_cg = lane >> 4;               // A: 16 rows x 2 kgroups
    const int b_nt = lane >> 4, b_half = (lane >> 3) & 1, b_r = lane & 7;

    load_stage(0, 0);

    for (int c = 0; c < NKCH; ++c) {
        const int st = c & 1;
        if (c + 1 < NKCH) { load_stage(c + 1, st ^ 1); cp_wait<1>(); }
        else              { cp_wait<0>(); }
        __syncthreads();

        const uint32_t stg = sb + st * STG_B;
        const uint32_t tAH = stg + OFF_AH, tAL = stg + OFF_AL;
        const uint32_t tBH = stg + OFF_BH, tBL = stg + OFF_BL;

#pragma unroll
        for (int ks = 0; ks < 2; ks++) {
            const int k16 = ks * 16;
            // B addresses for this k-step
            uint32_t bAddrOff[2];
#pragma unroll
            for (int bj = 0; bj < 2; bj++)
                bAddrOff[bj] = (uint32_t)(((wn * 32 + bj * 16 + b_nt * 8 + b_r) * LDT
                                           + k16 + b_half * 8) * 2);
            uint32_t aAddrOff[4];
#pragma unroll
            for (int mi = 0; mi < 4; mi++)
                aAddrOff[mi] = (uint32_t)(((wm * 64 + mi * 16 + a_r) * LDT
                                           + k16 + a_cg * 8) * 2);

            uint32_t aH[4][4];
#pragma unroll
            for (int mi = 0; mi < 4; mi++) ldm_x4(aH[mi], tAH + aAddrOff[mi]);
            uint32_t bH[2][4];
#pragma unroll
            for (int bj = 0; bj < 2; bj++) ldm_x4(bH[bj], tBH + bAddrOff[bj]);
            // term 1: Ah * Bh
#pragma unroll
            for (int mi = 0; mi < 4; mi++)
#pragma unroll
                for (int bj = 0; bj < 2; bj++) {
                    mma_bf16(acc[mi][bj * 2 + 0], aH[mi], bH[bj][0], bH[bj][1]);
                    mma_bf16(acc[mi][bj * 2 + 1], aH[mi], bH[bj][2], bH[bj][3]);
                }
            // term 2: Ah * Bl
            uint32_t bL[2][4];
#pragma unroll
            for (int bj = 0; bj < 2; bj++) ldm_x4(bL[bj], tBL + bAddrOff[bj]);
#pragma unroll
            for (int mi = 0; mi < 4; mi++)
#pragma unroll
                for (int bj = 0; bj < 2; bj++) {
                    mma_bf16(acc[mi][bj * 2 + 0], aH[mi], bL[bj][0], bL[bj][1]);
                    mma_bf16(acc[mi][bj * 2 + 1], aH[mi], bL[bj][2], bL[bj][3]);
                }
            // term 3: Al * Bh
            uint32_t aL[4][4];
#pragma unroll
            for (int mi = 0; mi < 4; mi++) ldm_x4(aL[mi], tAL + aAddrOff[mi]);
#pragma unroll
            for (int mi = 0; mi < 4; mi++)
#pragma unroll
                for (int bj = 0; bj < 2; bj++) {
                    mma_bf16(acc[mi][bj * 2 + 0], aL[mi], bH[bj][0], bH[bj][1]);
                    mma_bf16(acc[mi][bj * 2 + 1], aL[mi], bH[bj][2], bH[bj][3]);
                }
        }
        __syncthreads();
    }

    // epilogue: fragment layout c0,c1 -> (row l/4, col 2(l%4)+{0,1}); c2,c3 -> row+8
    const int er = lane >> 2, ec = (lane & 3) * 2;
#pragma unroll
    for (int mi = 0; mi < 4; mi++) {
#pragma unroll
        for (int j = 0; j < 4; j++) {
            int col = n0 + wn * 32 + j * 8 + ec;
            int r0 = m0 + wm * 64 + mi * 16 + er;
            float2 o0, o1;
            o0.x = acc[mi][j][0] + __ldg(bias + col);
            o0.y = acc[mi][j][1] + __ldg(bias + col + 1);
            o1.x = acc[mi][j][2] + __ldg(bias + col);
            o1.y = acc[mi][j][3] + __ldg(bias + col + 1);
            *(float2*)&Cout[(size_t)r0 * Cdim + col] = o0;
            *(float2*)&Cout[(size_t)(r0 + 8) * Cdim + col] = o1;
        }
    }
}

// ---------------------------------------------------------------------------
// Flash attention (causal) fp32 — unchanged (verified in R1/R2)
// ---------------------------------------------------------------------------
#define BQ 64
#define BK 64
#define KS 68

extern __shared__ float fsh[];

__global__ __launch_bounds__(256) void flash_kernel(
    const float* __restrict__ Q, const float* __restrict__ Kg,
    const float* __restrict__ V, float* __restrict__ Y)
{
    float* Qs = fsh;
    float* Ks = Qs + BQ * KS;
    float* Vs = Ks + BK * KS;
    float* Ps = Vs + BK * KS;

    const int tid = threadIdx.x;
    const int tx = tid & 15;
    const int ty = tid >> 4;
    const int qt = blockIdx.x;
    const int h  = blockIdx.y;
    const int b  = blockIdx.z;
    const int q0 = qt * BQ;

    const float* Qb = Q + ((size_t)b * Tdim) * Cdim + h * HDdim;
    const float* Kb = Kg + ((size_t)b * Tdim) * Cdim + h * HDdim;
    const float* Vb = V + ((size_t)b * Tdim) * Cdim + h * HDdim;

    {
        int c = (tid & 15) * 4;
        for (int r = tid >> 4; r < BQ; r += 16) {
            float4 v = *(const float4*)(Qb + (size_t)(q0 + r) * Cdim + c);
            v.x *= SCALE; v.y *= SCALE; v.z *= SCALE; v.w *= SCALE;
            *(float4*)&Qs[r * KS + c] = v;
        }
    }

    float m[4], l[4], O[4][4];
#pragma unroll
    for (int i = 0; i < 4; i++) {
        m[i] = -INFINITY; l[i] = 0.0f;
#pragma unroll
        for (int j = 0; j < 4; j++) O[i][j] = 0.0f;
    }

    for (int kt = 0; kt <= qt; ++kt) {
        __syncthreads();
        const int k0 = kt * BK;
        {
            int c = (tid & 15) * 4;
            for (int r = tid >> 4; r < BK; r += 16) {
                *(float4*)&Ks[r * KS + c] =
                    *(const float4*)(Kb + (size_t)(k0 + r) * Cdim + c);
                *(float4*)&Vs[r * KS + c] =
                    *(const float4*)(Vb + (size_t)(k0 + r) * Cdim + c);
            }
        }
        __syncthreads();

        float s[4][4];
#pragma unroll
        for (int i = 0; i < 4; i++)
#pragma unroll
            for (int j = 0; j < 4; j++) s[i][j] = 0.0f;

#pragma unroll
        for (int d0 = 0; d0 < HDdim; d0 += 4) {
            float4 qf[4], kf[4];
#pragma unroll
            for (int i = 0; i < 4; i++)
                qf[i] = *(const float4*)&Qs[(ty * 4 + i) * KS + d0];
#pragma unroll
            for (int j = 0; j < 4; j++)
                kf[j] = *(const float4*)&Ks[(tx + 16 * j) * KS + d0];
#pragma unroll
            for (int i = 0; i < 4; i++)
#pragma unroll
                for (int j = 0; j < 4; j++) {
                    s[i][j] += qf[i].x * kf[j].x;
                    s[i][j] += qf[i].y * kf[j].y;
                    s[i][j] += qf[i].z * kf[j].z;
                    s[i][j] += qf[i].w * kf[j].w;
                }
        }

        if (kt == qt) {
#pragma unroll
            for (int i = 0; i < 4; i++)
#pragma unroll
                for (int j = 0; j < 4; j++)
                    if (tx + 16 * j > ty * 4 + i) s[i][j] = -INFINITY;
        }

#pragma unroll
        for (int i = 0; i < 4; i++) {
            float rm = fmaxf(fmaxf(s[i][0], s[i][1]), fmaxf(s[i][2], s[i][3]));
#pragma unroll
            for (int off = 8; off > 0; off >>= 1)
                rm = fmaxf(rm, __shfl_xor_sync(0xffffffffu, rm, off));
            float mn = fmaxf(m[i], rm);
            float corr = __expf(m[i] - mn);
            float p[4];
            float rs = 0.0f;
#pragma unroll
            for (int j = 0; j < 4; j++) { p[j] = __expf(s[i][j] - mn); rs += p[j]; }
#pragma unroll
            for (int off = 8; off > 0; off >>= 1)
                rs += __shfl_xor_sync(0xffffffffu, rs, off);
            l[i] = l[i] * corr + rs;
            m[i] = mn;
#pragma unroll
            for (int j = 0; j < 4; j++) O[i][j] *= corr;
            Ps[(ty * 4 + i) * KS + tx +  0] = p[0];
            Ps[(ty * 4 + i) * KS + tx + 16] = p[1];
            Ps[(ty * 4 + i) * KS + tx + 32] = p[2];
            Ps[(ty * 4 + i) * KS + tx + 48] = p[3];
        }
        __syncthreads();

#pragma unroll
        for (int k4 = 0; k4 < BK; k4 += 4) {
            float pf[4][4];
#pragma unroll
            for (int i = 0; i < 4; i++)
                *(float4*)&pf[i][0] = *(const float4*)&Ps[(ty * 4 + i) * KS + k4];
#pragma unroll
            for (int kk = 0; kk < 4; kk++) {
                float vf[4];
                *(float4*)&vf[0] = *(const float4*)&Vs[(k4 + kk) * KS + tx * 4];
#pragma unroll
                for (int i = 0; i < 4; i++)
#pragma unroll
                    for (int j = 0; j < 4; j++)
                        O[i][j] += pf[i][kk] * vf[j];
            }
        }
    }

#pragma unroll
    for (int i = 0; i < 4; i++) {
        float inv = 1.0f / l[i];
        float4 o;
        o.x = O[i][0] * inv; o.y = O[i][1] * inv;
        o.z = O[i][2] * inv; o.w = O[i][3] * inv;
        *(float4*)&Y[((size_t)b * Tdim + q0 + ty * 4 + i) * Cdim + h * HDdim + tx * 4] = o;
    }
}

// ---------------------------------------------------------------------------
// Launch
// ---------------------------------------------------------------------------
extern "C" void kernel_launch(void* const* d_in, const int* in_sizes, int n_in,
                              void* d_out, int out_size)
{
    const float* query = (const float*)d_in[0];
    const float* key_  = (const float*)d_in[1];
    const float* value = (const float*)d_in[2];
    const float* Wq = (const float*)d_in[4];
    const float* bq = (const float*)d_in[5];
    const float* Wk = (const float*)d_in[6];
    const float* bk = (const float*)d_in[7];
    const float* Wv = (const float*)d_in[8];
    const float* bv = (const float*)d_in[9];
    const float* Wp = (const float*)d_in[10];
    const float* bp = (const float*)d_in[11];
    float* out = (float*)d_out;

    float *q, *k, *v, *y;
    __nv_bfloat16 *ah, *al, *wh, *wl;
    cudaGetSymbolAddress((void**)&q,  g_q);
    cudaGetSymbolAddress((void**)&k,  g_k);
    cudaGetSymbolAddress((void**)&v,  g_v);
    cudaGetSymbolAddress((void**)&y,  g_y);
    cudaGetSymbolAddress((void**)&ah, g_ah);
    cudaGetSymbolAddress((void**)&al, g_al);
    cudaGetSymbolAddress((void**)&wh, g_wh);
    cudaGetSymbolAddress((void**)&wl, g_wl);

    cudaFuncSetAttribute(gemm_tc_kernel,
                         cudaFuncAttributeMaxDynamicSharedMemorySize, GEMM_SMEM);

    const int n4 = Mrows * Cdim / 4;
    dim3 cgrid(n4 / 256);
    dim3 wgrid(Cdim / 32, Cdim / 32);
    dim3 wblk(32, 8);
    dim3 ggrid(Cdim / BN, Mrows / BM);   // (8, 32)

    // Q projection
    conv_split_kernel<<<cgrid, 256>>>(query, ah, al, n4);
    conv_wT_kernel<<<wgrid, wblk>>>(Wq, wh, wl);
    gemm_tc_kernel<<<ggrid, 256, GEMM_SMEM>>>(ah, al, wh, wl, bq, q);
    // K projection
    conv_split_kernel<<<cgrid, 256>>>(key_, ah, al, n4);
    conv_wT_kernel<<<wgrid, wblk>>>(Wk, wh, wl);
    gemm_tc_kernel<<<ggrid, 256, GEMM_SMEM>>>(ah, al, wh, wl, bk, k);
    // V projection
    conv_split_kernel<<<cgrid, 256>>>(value, ah, al, n4);
    conv_wT_kernel<<<wgrid, wblk>>>(Wv, wh, wl);
    gemm_tc_kernel<<<ggrid, 256, GEMM_SMEM>>>(ah, al, wh, wl, bv, v);

    // attention
    const int fsm = 4 * 64 * KS * (int)sizeof(float);
    cudaFuncSetAttribute(flash_kernel,
                         cudaFuncAttributeMaxDynamicSharedMemorySize, fsm);
    flash_kernel<<<dim3(Tdim / BQ, Hdim, Bdim), 256, fsm>>>(q, k, v, y);

    // output projection
    conv_split_kernel<<<cgrid, 256>>>(y, ah, al, n4);
    conv_wT_kernel<<<wgrid, wblk>>>(Wp, wh, wl);
    gemm_tc_kernel<<<ggrid, 256, GEMM_SMEM>>>(ah, al, wh, wl, bp, out);
}

// round 9
// speedup vs baseline: 2.5471x; 1.7079x over previous
#include <cuda_runtime.h>
#include <cuda_bf16.h>
#include <stdint.h>
#include <math.h>

#define Bdim 2
#define Tdim 2048
#define Cdim 1024
#define Hdim 16
#define HDdim 64
#define QSCALE 0.125f   // (1/ALPHA/sqrt(HD)) * ALPHA == 1/sqrt(64)
#define NEGINF __int_as_float(0xff800000)

#define Mrows (Bdim * Tdim)   // 4096

// ---------------- device scratch (no allocation allowed) -------------------
__device__ float g_q[Mrows * Cdim];
__device__ float g_k[Mrows * Cdim];
__device__ float g_v[Mrows * Cdim];
__device__ float g_vt[Mrows * Cdim];   // V transposed per batch: [B][C][T]
__device__ float g_y[Mrows * Cdim];
__device__ __nv_bfloat16 g_ah[Mrows * Cdim];
__device__ __nv_bfloat16 g_al[Mrows * Cdim];
__device__ __nv_bfloat16 g_wh[Cdim * Cdim];
__device__ __nv_bfloat16 g_wl[Cdim * Cdim];

// ---------------------------------------------------------------------------
// Portable PTX helpers (compute_103 virtual arch safe)
// ---------------------------------------------------------------------------
__device__ __forceinline__ void cp16(uint32_t dst, const void* src) {
    asm volatile("cp.async.cg.shared.global [%0], [%1], 16;" :: "r"(dst), "l"(src));
}
__device__ __forceinline__ void cp_commit() {
    asm volatile("cp.async.commit_group;" ::: "memory");
}
template <int N>
__device__ __forceinline__ void cp_wait() {
    asm volatile("cp.async.wait_group %0;" :: "n"(N) : "memory");
}
__device__ __forceinline__ void ldm_x4(uint32_t f[4], uint32_t addr) {
    asm volatile("ldmatrix.sync.aligned.m8n8.x4.shared.b16 {%0,%1,%2,%3}, [%4];"
                 : "=r"(f[0]), "=r"(f[1]), "=r"(f[2]), "=r"(f[3]) : "r"(addr));
}
__device__ __forceinline__ void mma_bf16(float c[4], const uint32_t a[4],
                                         const uint32_t b0, const uint32_t b1) {
    asm volatile(
        "mma.sync.aligned.m16n8k16.row.col.f32.bf16.bf16.f32 "
        "{%0,%1,%2,%3}, {%4,%5,%6,%7}, {%8,%9}, {%0,%1,%2,%3};"
        : "+f"(c[0]), "+f"(c[1]), "+f"(c[2]), "+f"(c[3])
        : "r"(a[0]), "r"(a[1]), "r"(a[2]), "r"(a[3]), "r"(b0), "r"(b1));
}
__device__ __forceinline__ void mma_tf32(float c[4], uint32_t a0, uint32_t a1,
                                         uint32_t a2, uint32_t a3,
                                         uint32_t b0, uint32_t b1) {
    asm volatile(
        "mma.sync.aligned.m16n8k8.row.col.f32.tf32.tf32.f32 "
        "{%0,%1,%2,%3}, {%4,%5,%6,%7}, {%8,%9}, {%0,%1,%2,%3};"
        : "+f"(c[0]), "+f"(c[1]), "+f"(c[2]), "+f"(c[3])
        : "r"(a0), "r"(a1), "r"(a2), "r"(a3), "r"(b0), "r"(b1));
}
__device__ __forceinline__ float tf32r(float x) {
    uint32_t u;
    asm("cvt.rna.tf32.f32 %0, %1;" : "=r"(u) : "f"(x));
    return __uint_as_float(u);
}
__device__ __forceinline__ uint32_t tf32u(float x) {
    uint32_t u;
    asm("cvt.rna.tf32.f32 %0, %1;" : "=r"(u) : "f"(x));
    return u;
}

// ---------------------------------------------------------------------------
// Conversion kernels (for bf16x3 GEMM path)
// ---------------------------------------------------------------------------
__global__ __launch_bounds__(256) void conv_split_kernel(
    const float* __restrict__ x, __nv_bfloat16* __restrict__ h,
    __nv_bfloat16* __restrict__ l, int n4)
{
    int i = blockIdx.x * 256 + threadIdx.x;
    if (i >= n4) return;
    float4 v = ((const float4*)x)[i];
    union { __nv_bfloat16 b[4]; uint2 u; } H, L;
    float vv[4] = {v.x, v.y, v.z, v.w};
#pragma unroll
    for (int j = 0; j < 4; j++) {
        H.b[j] = __float2bfloat16_rn(vv[j]);
        L.b[j] = __float2bfloat16_rn(vv[j] - __bfloat162float(H.b[j]));
    }
    ((uint2*)h)[i] = H.u;
    ((uint2*)l)[i] = L.u;
}

__global__ __launch_bounds__(256) void conv_wT_kernel(
    const float* __restrict__ W, __nv_bfloat16* __restrict__ ht,
    __nv_bfloat16* __restrict__ lt)
{
    __shared__ float t[32][33];
    int n0 = blockIdx.x * 32, k0 = blockIdx.y * 32;
    int tx = threadIdx.x, ty = threadIdx.y;
#pragma unroll
    for (int r = 0; r < 32; r += 8)
        t[ty + r][tx] = W[(size_t)(k0 + ty + r) * Cdim + n0 + tx];
    __syncthreads();
#pragma unroll
    for (int r = 0; r < 32; r += 8) {
        float v = t[tx][ty + r];
        __nv_bfloat16 hb = __float2bfloat16_rn(v);
        size_t o = (size_t)(n0 + ty + r) * Cdim + k0 + tx;
        ht[o] = hb;
        lt[o] = __float2bfloat16_rn(v - __bfloat162float(hb));
    }
}

// v [B][T][C] -> vt [B][C][T]  (fp32, values already tf32-rounded)
__global__ __launch_bounds__(256) void transpose_kernel(
    const float* __restrict__ v, float* __restrict__ vt)
{
    __shared__ float t[32][33];
    int c0 = blockIdx.x * 32, t0 = blockIdx.y * 32, b = blockIdx.z;
    int tx = threadIdx.x, ty = threadIdx.y;
#pragma unroll
    for (int r = 0; r < 32; r += 8)
        t[ty + r][tx] = v[((size_t)b * Tdim + t0 + ty + r) * Cdim + c0 + tx];
    __syncthreads();
#pragma unroll
    for (int r = 0; r < 32; r += 8)
        vt[((size_t)b * Cdim + c0 + ty + r) * Tdim + t0 + tx] = t[tx][ty + r];
}

// ---------------------------------------------------------------------------
// HMMA bf16x3 GEMM (unchanged core; epilogue gains tf32-round + scale)
// ---------------------------------------------------------------------------
#define BM 128
#define BN 128
#define BKc 32
#define LDT 40
#define TILE_B (128 * LDT * 2)
#define STG_B (4 * TILE_B)
#define OFF_AH 0
#define OFF_AL TILE_B
#define OFF_BH (2 * TILE_B)
#define OFF_BL (3 * TILE_B)
#define GEMM_SMEM (2 * STG_B)
#define NKCH (Cdim / BKc)

extern __shared__ __align__(128) char gsm[];

__global__ __launch_bounds__(256) void gemm_tc_kernel(
    const __nv_bfloat16* __restrict__ Ah, const __nv_bfloat16* __restrict__ Al,
    const __nv_bfloat16* __restrict__ Bh, const __nv_bfloat16* __restrict__ Bl,
    const float* __restrict__ bias, float* __restrict__ Cout,
    float oscale, int oround)
{
    const int tid = threadIdx.x;
    const int lane = tid & 31;
    const int wid = tid >> 5;
    const int wm = wid >> 2;
    const int wn = wid & 3;
    const int m0 = blockIdx.y * BM;
    const int n0 = blockIdx.x * BN;
    const uint32_t sb = (uint32_t)__cvta_generic_to_shared(gsm);

    const __nv_bfloat16* srcA[2] = {Ah, Al};
    const __nv_bfloat16* srcB[2] = {Bh, Bl};

    auto load_stage = [&](int c, int st) {
        const int kc = c * BKc;
        const uint32_t base = sb + st * STG_B;
#pragma unroll
        for (int it = 0; it < 8; it++) {
            int id = tid + it * 256;
            int tile = id >> 9;
            int rem = id & 511;
            int row = rem >> 2;
            int grp = rem & 3;
            uint32_t dst = base + tile * TILE_B + (row * LDT + grp * 8) * 2;
            const __nv_bfloat16* s;
            if (tile < 2) s = srcA[tile] + (size_t)(m0 + row) * Cdim + kc + grp * 8;
            else          s = srcB[tile - 2] + (size_t)(n0 + row) * Cdim + kc + grp * 8;
            cp16(dst, s);
        }
        cp_commit();
    };

    float acc[4][4][4];
#pragma unroll
    for (int i = 0; i < 4; i++)
#pragma unroll
        for (int j = 0; j < 4; j++)
#pragma unroll
            for (int r = 0; r < 4; r++) acc[i][j][r] = 0.0f;

    const int a_r = lane & 15, a_cg = lane >> 4;
    const int b_nt = lane >> 4, b_half = (lane >> 3) & 1, b_r = lane & 7;

    load_stage(0, 0);

    for (int c = 0; c < NKCH; ++c) {
        const int st = c & 1;
        if (c + 1 < NKCH) { load_stage(c + 1, st ^ 1); cp_wait<1>(); }
        else              { cp_wait<0>(); }
        __syncthreads();

        const uint32_t stg = sb + st * STG_B;
        const uint32_t tAH = stg + OFF_AH, tAL = stg + OFF_AL;
        const uint32_t tBH = stg + OFF_BH, tBL = stg + OFF_BL;

#pragma unroll
        for (int ks = 0; ks < 2; ks++) {
            const int k16 = ks * 16;
            uint32_t bAddrOff[2];
#pragma unroll
            for (int bj = 0; bj < 2; bj++)
                bAddrOff[bj] = (uint32_t)(((wn * 32 + bj * 16 + b_nt * 8 + b_r) * LDT
                                           + k16 + b_half * 8) * 2);
            uint32_t aAddrOff[4];
#pragma unroll
            for (int mi = 0; mi < 4; mi++)
                aAddrOff[mi] = (uint32_t)(((wm * 64 + mi * 16 + a_r) * LDT
                                           + k16 + a_cg * 8) * 2);

            uint32_t aH[4][4];
#pragma unroll
            for (int mi = 0; mi < 4; mi++) ldm_x4(aH[mi], tAH + aAddrOff[mi]);
            uint32_t bH[2][4];
#pragma unroll
            for (int bj = 0; bj < 2; bj++) ldm_x4(bH[bj], tBH + bAddrOff[bj]);
#pragma unroll
            for (int mi = 0; mi < 4; mi++)
#pragma unroll
                for (int bj = 0; bj < 2; bj++) {
                    mma_bf16(acc[mi][bj * 2 + 0], aH[mi], bH[bj][0], bH[bj][1]);
                    mma_bf16(acc[mi][bj * 2 + 1], aH[mi], bH[bj][2], bH[bj][3]);
                }
            uint32_t bL[2][4];
#pragma unroll
            for (int bj = 0; bj < 2; bj++) ldm_x4(bL[bj], tBL + bAddrOff[bj]);
#pragma unroll
            for (int mi = 0; mi < 4; mi++)
#pragma unroll
                for (int bj = 0; bj < 2; bj++) {
                    mma_bf16(acc[mi][bj * 2 + 0], aH[mi], bL[bj][0], bL[bj][1]);
                    mma_bf16(acc[mi][bj * 2 + 1], aH[mi], bL[bj][2], bL[bj][3]);
                }
            uint32_t aL[4][4];
#pragma unroll
            for (int mi = 0; mi < 4; mi++) ldm_x4(aL[mi], tAL + aAddrOff[mi]);
#pragma unroll
            for (int mi = 0; mi < 4; mi++)
#pragma unroll
                for (int bj = 0; bj < 2; bj++) {
                    mma_bf16(acc[mi][bj * 2 + 0], aL[mi], bH[bj][0], bH[bj][1]);
                    mma_bf16(acc[mi][bj * 2 + 1], aL[mi], bH[bj][2], bH[bj][3]);
                }
        }
        __syncthreads();
    }

    const int er = lane >> 2, ec = (lane & 3) * 2;
#pragma unroll
    for (int mi = 0; mi < 4; mi++) {
#pragma unroll
        for (int j = 0; j < 4; j++) {
            int col = n0 + wn * 32 + j * 8 + ec;
            int r0 = m0 + wm * 64 + mi * 16 + er;
            float b0 = __ldg(bias + col), b1 = __ldg(bias + col + 1);
            float2 o0, o1;
            o0.x = acc[mi][j][0] + b0;
            o0.y = acc[mi][j][1] + b1;
            o1.x = acc[mi][j][2] + b0;
            o1.y = acc[mi][j][3] + b1;
            if (oround) {
                o0.x = tf32r(o0.x * oscale); o0.y = tf32r(o0.y * oscale);
                o1.x = tf32r(o1.x * oscale); o1.y = tf32r(o1.y * oscale);
            }
            *(float2*)&Cout[(size_t)r0 * Cdim + col] = o0;
            *(float2*)&Cout[(size_t)(r0 + 8) * Cdim + col] = o1;
        }
    }
}

// ---------------------------------------------------------------------------
// Flash attention v2 (causal) on tensor cores, tf32 single-pass.
// CTA: 128 q-rows, one (head, batch). 8 warps x 16 rows. BK=64 keys/iter.
// Q,K,V pre-rounded to tf32 in GEMM epilogue; V pre-transposed (g_vt).
// ---------------------------------------------------------------------------
#define FBQ 128
#define FBK 64
#define LDF 68
#define FQ_BYTES (FBQ * LDF * 4)          // 34816
#define FK_BYTES (FBK * LDF * 4)          // 17408
#define FSTG (2 * FK_BYTES)               // K + VT per stage
#define FLASH_SMEM (FQ_BYTES + 2 * FSTG)  // 104448

__global__ __launch_bounds__(256, 1) void flash_tc_kernel(
    const float* __restrict__ Q, const float* __restrict__ Kg,
    const float* __restrict__ VT, float* __restrict__ Y)
{
    const int tid = threadIdx.x;
    const int lane = tid & 31;
    const int wid = tid >> 5;
    const int qt = gridDim.x - 1 - blockIdx.x;   // long CTAs first
    const int h = blockIdx.y;
    const int b = blockIdx.z;
    const int qb = qt * FBQ;
    const uint32_t sb = (uint32_t)__cvta_generic_to_shared(gsm);

    // lane geometry shared by all fragment ldmatrix ops (f32-as-b16 trick)
    const int laneRow = (lane & 7) + 8 * (lane >> 4);
    const uint32_t laneCol = 16u * ((lane >> 3) & 1);
    const int lq = lane & 3;          // quad index
    const int lr = lane >> 2;         // row-in-8

    // ---- load Q tile (128 x 64 f32) ----
#pragma unroll
    for (int it = 0; it < 8; it++) {
        int id = tid + it * 256;
        int row = id >> 4, j = id & 15;
        cp16(sb + (uint32_t)(row * LDF + 4 * j) * 4,
             Q + ((size_t)b * Tdim + qb + row) * Cdim + h * HDdim + 4 * j);
    }
    cp_commit();

    const uint32_t stage0 = sb + FQ_BYTES;

    auto load_kv = [&](int kt, int st) {
        const int k0 = kt * FBK;
        const uint32_t base = stage0 + st * FSTG;
#pragma unroll
        for (int it = 0; it < 8; it++) {
            int id = tid + it * 256;
            int tile = id >> 10;
            int rem = id & 1023;
            int row = rem >> 4, j = rem & 15;
            uint32_t dst = base + tile * FK_BYTES + (uint32_t)(row * LDF + 4 * j) * 4;
            const float* src;
            if (tile == 0)
                src = Kg + ((size_t)b * Tdim + k0 + row) * Cdim + h * HDdim + 4 * j;
            else
                src = VT + ((size_t)b * Cdim + h * HDdim + row) * Tdim + k0 + 4 * j;
            cp16(dst, src);
        }
        cp_commit();
    };

    const int nkt = 2 * qt + 2;
    load_kv(0, 0);

    // wait for Q (leave stage0 pending), then build Q fragments (held all kernel)
    cp_wait<1>();
    __syncthreads();
    uint32_t qf[8][4];
    {
        uint32_t qbase = sb + (uint32_t)((16 * wid + laneRow) * LDF) * 4 + laneCol;
#pragma unroll
        for (int g = 0; g < 8; g++) ldm_x4(qf[g], qbase + 32 * g);
    }

    float oA[8][4];
#pragma unroll
    for (int nt = 0; nt < 8; nt++)
#pragma unroll
        for (int r = 0; r < 4; r++) oA[nt][r] = 0.0f;
    float m0 = NEGINF, m1 = NEGINF, l0 = 0.0f, l1 = 0.0f;

    const int qw0 = qb + 16 * wid;   // first q row of this warp

    for (int kt = 0; kt < nkt; kt++) {
        const int st = kt & 1;
        if (kt + 1 < nkt) { load_kv(kt + 1, st ^ 1); cp_wait<1>(); }
        else              { cp_wait<0>(); }
        __syncthreads();

        const int k0 = kt * FBK;
        if (k0 <= qw0 + 15) {   // else fully masked for this warp: skip
            const uint32_t kst = stage0 + st * FSTG;
            const uint32_t vst = kst + FK_BYTES;

            // ---- S = Q K^T  (16 x 64 per warp) ----
            float s[8][4];
#pragma unroll
            for (int nt = 0; nt < 8; nt++)
#pragma unroll
                for (int r = 0; r < 4; r++) s[nt][r] = 0.0f;

#pragma unroll
            for (int g = 0; g < 8; g++) {
#pragma unroll
                for (int ntp = 0; ntp < 4; ntp++) {
                    uint32_t kb[4];
                    ldm_x4(kb, kst + (uint32_t)((16 * ntp + laneRow) * LDF) * 4
                               + 32 * g + laneCol);
                    mma_tf32(s[2 * ntp],     qf[g][0], qf[g][2], qf[g][1], qf[g][3],
                             kb[0], kb[1]);
                    mma_tf32(s[2 * ntp + 1], qf[g][0], qf[g][2], qf[g][1], qf[g][3],
                             kb[2], kb[3]);
                }
            }

            // ---- causal mask (boundary tiles only) ----
            if (k0 + FBK - 1 > qw0) {
#pragma unroll
                for (int nt = 0; nt < 8; nt++)
#pragma unroll
                    for (int r = 0; r < 4; r++) {
                        int col = k0 + 8 * nt + 2 * lq + (r & 1);
                        int row = qw0 + lr + 8 * (r >> 1);
                        if (col > row) s[nt][r] = NEGINF;
                    }
            }

            // ---- online softmax ----
            float mx0 = NEGINF, mx1 = NEGINF;
#pragma unroll
            for (int nt = 0; nt < 8; nt++) {
                mx0 = fmaxf(mx0, fmaxf(s[nt][0], s[nt][1]));
                mx1 = fmaxf(mx1, fmaxf(s[nt][2], s[nt][3]));
            }
            mx0 = fmaxf(mx0, __shfl_xor_sync(0xffffffffu, mx0, 1));
            mx0 = fmaxf(mx0, __shfl_xor_sync(0xffffffffu, mx0, 2));
            mx1 = fmaxf(mx1, __shfl_xor_sync(0xffffffffu, mx1, 1));
            mx1 = fmaxf(mx1, __shfl_xor_sync(0xffffffffu, mx1, 2));
            float mn0 = fmaxf(m0, mx0), mn1 = fmaxf(m1, mx1);
            float c0 = __expf(m0 - mn0), c1 = __expf(m1 - mn1);
            float rs0 = 0.0f, rs1 = 0.0f;
#pragma unroll
            for (int nt = 0; nt < 8; nt++) {
                oA[nt][0] *= c0; oA[nt][1] *= c0;
                oA[nt][2] *= c1; oA[nt][3] *= c1;
                s[nt][0] = __expf(s[nt][0] - mn0);
                s[nt][1] = __expf(s[nt][1] - mn0);
                s[nt][2] = __expf(s[nt][2] - mn1);
                s[nt][3] = __expf(s[nt][3] - mn1);
                rs0 += s[nt][0] + s[nt][1];
                rs1 += s[nt][2] + s[nt][3];
            }
            rs0 += __shfl_xor_sync(0xffffffffu, rs0, 1);
            rs0 += __shfl_xor_sync(0xffffffffu, rs0, 2);
            rs1 += __shfl_xor_sync(0xffffffffu, rs1, 1);
            rs1 += __shfl_xor_sync(0xffffffffu, rs1, 2);
            l0 = l0 * c0 + rs0;
            l1 = l1 * c1 + rs1;
            m0 = mn0; m1 = mn1;

            // ---- O += P V : rebuild P as tf32 A-fragments via shfl ----
            const int srcA0 = (lane & ~3) | (lq >> 1);
            const int srcA2 = srcA0 + 2;
            const bool odd = (lane & 1);
#pragma unroll
            for (int g = 0; g < 8; g++) {
                uint32_t p0 = tf32u(s[g][0]), p1 = tf32u(s[g][1]);
                uint32_t p2 = tf32u(s[g][2]), p3 = tf32u(s[g][3]);
                uint32_t e, o;
                e = __shfl_sync(0xffffffffu, p0, srcA0);
                o = __shfl_sync(0xffffffffu, p1, srcA0);
                uint32_t a0 = odd ? o : e;
                e = __shfl_sync(0xffffffffu, p2, srcA0);
                o = __shfl_sync(0xffffffffu, p3, srcA0);
                uint32_t a1 = odd ? o : e;
                e = __shfl_sync(0xffffffffu, p0, srcA2);
                o = __shfl_sync(0xffffffffu, p1, srcA2);
                uint32_t a2 = odd ? o : e;
                e = __shfl_sync(0xffffffffu, p2, srcA2);
                o = __shfl_sync(0xffffffffu, p3, srcA2);
                uint32_t a3 = odd ? o : e;
#pragma unroll
                for (int ntp = 0; ntp < 4; ntp++) {
                    uint32_t vb[4];
                    ldm_x4(vb, vst + (uint32_t)((16 * ntp + laneRow) * LDF) * 4
                               + 32 * g + laneCol);
                    mma_tf32(oA[2 * ntp],     a0, a1, a2, a3, vb[0], vb[1]);
                    mma_tf32(oA[2 * ntp + 1], a0, a1, a2, a3, vb[2], vb[3]);
                }
            }
        }
        __syncthreads();
    }

    // ---- epilogue ----
    float inv0 = 1.0f / l0, inv1 = 1.0f / l1;
    int row0 = qw0 + lr;
    int row1 = row0 + 8;
#pragma unroll
    for (int nt = 0; nt < 8; nt++) {
        int col = h * HDdim + 8 * nt + 2 * lq;
        float2 w0, w1;
        w0.x = oA[nt][0] * inv0; w0.y = oA[nt][1] * inv0;
        w1.x = oA[nt][2] * inv1; w1.y = oA[nt][3] * inv1;
        *(float2*)&Y[((size_t)b * Tdim + row0) * Cdim + col] = w0;
        *(float2*)&Y[((size_t)b * Tdim + row1) * Cdim + col] = w1;
    }
}

// ---------------------------------------------------------------------------
// Launch
// ---------------------------------------------------------------------------
extern "C" void kernel_launch(void* const* d_in, const int* in_sizes, int n_in,
                              void* d_out, int out_size)
{
    const float* query = (const float*)d_in[0];
    const float* key_  = (const float*)d_in[1];
    const float* value = (const float*)d_in[2];
    const float* Wq = (const float*)d_in[4];
    const float* bq = (const float*)d_in[5];
    const float* Wk = (const float*)d_in[6];
    const float* bk = (const float*)d_in[7];
    const float* Wv = (const float*)d_in[8];
    const float* bv = (const float*)d_in[9];
    const float* Wp = (const float*)d_in[10];
    const float* bp = (const float*)d_in[11];
    float* out = (float*)d_out;

    float *q, *k, *v, *vt, *y;
    __nv_bfloat16 *ah, *al, *wh, *wl;
    cudaGetSymbolAddress((void**)&q,  g_q);
    cudaGetSymbolAddress((void**)&k,  g_k);
    cudaGetSymbolAddress((void**)&v,  g_v);
    cudaGetSymbolAddress((void**)&vt, g_vt);
    cudaGetSymbolAddress((void**)&y,  g_y);
    cudaGetSymbolAddress((void**)&ah, g_ah);
    cudaGetSymbolAddress((void**)&al, g_al);
    cudaGetSymbolAddress((void**)&wh, g_wh);
    cudaGetSymbolAddress((void**)&wl, g_wl);

    cudaFuncSetAttribute(gemm_tc_kernel,
                         cudaFuncAttributeMaxDynamicSharedMemorySize, GEMM_SMEM);
    cudaFuncSetAttribute(flash_tc_kernel,
                         cudaFuncAttributeMaxDynamicSharedMemorySize, FLASH_SMEM);

    const int n4 = Mrows * Cdim / 4;
    dim3 cgrid(n4 / 256);
    dim3 wgrid(Cdim / 32, Cdim / 32);
    dim3 wblk(32, 8);
    dim3 ggrid(Cdim / BN, Mrows / BM);

    // Q projection (epilogue: x0.125 then tf32-round)
    conv_split_kernel<<<cgrid, 256>>>(query, ah, al, n4);
    conv_wT_kernel<<<wgrid, wblk>>>(Wq, wh, wl);
    gemm_tc_kernel<<<ggrid, 256, GEMM_SMEM>>>(ah, al, wh, wl, bq, q, QSCALE, 1);
    // K projection (tf32-round)
    conv_split_kernel<<<cgrid, 256>>>(key_, ah, al, n4);
    conv_wT_kernel<<<wgrid, wblk>>>(Wk, wh, wl);
    gemm_tc_kernel<<<ggrid, 256, GEMM_SMEM>>>(ah, al, wh, wl, bk, k, 1.0f, 1);
    // V projection (tf32-round) + transpose
    conv_split_kernel<<<cgrid, 256>>>(value, ah, al, n4);
    conv_wT_kernel<<<wgrid, wblk>>>(Wv, wh, wl);
    gemm_tc_kernel<<<ggrid, 256, GEMM_SMEM>>>(ah, al, wh, wl, bv, v, 1.0f, 1);
    transpose_kernel<<<dim3(Cdim / 32, Tdim / 32, Bdim), wblk>>>(v, vt);

    // attention (tf32 tensor cores)
    flash_tc_kernel<<<dim3(Tdim / FBQ, Hdim, Bdim), 256, FLASH_SMEM>>>(q, k, vt, y);

    // output projection (plain fp32 epilogue)
    conv_split_kernel<<<cgrid, 256>>>(y, ah, al, n4);
    conv_wT_kernel<<<wgrid, wblk>>>(Wp, wh, wl);
    gemm_tc_kernel<<<ggrid, 256, GEMM_SMEM>>>(ah, al, wh, wl, bp, out, 1.0f, 0);
}